// round 1
// baseline (speedup 1.0000x reference)
#include <cuda_runtime.h>

#define BATCH  4
#define NPT    4096
#define CDIM   256
#define DDIM   128
#define NGROUP 50
#define BN     (BATCH*NPT)

// Output layout (flattened tuple, in reference-return order):
//   ptssemseg        : BN*NGROUP           = 819200
//   ptssemseg_logits : BN*NGROUP           = 819200
//   simmat_logits    : BATCH*NPT*NPT       = 67108864
//   conf             : BN                  = 16384
//   conf_logits      : BN                  = 16384
#define OFF_SOFT    0
#define OFF_LOGITS  819200
#define OFF_SIM     1638400
#define OFF_CONF    68747264
#define OFF_CONFLOG 68763648

// Scratch (device globals: allocation-free)
__device__ float g_Fsem[BN*DDIM];
__device__ float g_Fsim[BN*DDIM];
__device__ float g_Fconf[BN*DDIM];
__device__ float g_r[BN];

// ---------------------------------------------------------------------------
// Head GEMM: F = X @ W + b.   X: [BN, 256], W: [256, 128], F: [BN, 128]
// 64x64 tile, 256 threads, 4x4 microtile, K-chunks of 32.
// ---------------------------------------------------------------------------
template <int HEAD>
__global__ __launch_bounds__(256)
void head_gemm(const float* __restrict__ X,
               const float* __restrict__ W,
               const float* __restrict__ bias)
{
    float* Fout = (HEAD == 0) ? g_Fsem : (HEAD == 1) ? g_Fsim : g_Fconf;

    __shared__ __align__(16) float As[32*65];   // As[k][m], stride 65 (conflict-free)
    __shared__ __align__(16) float Bs[32*65];   // Bs[k][n], stride 65

    const int m0  = blockIdx.x * 64;
    const int n0  = blockIdx.y * 64;
    const int tid = threadIdx.x;
    const int tx  = tid & 15;       // n direction
    const int ty  = tid >> 4;       // m direction
    const int kkA = tid & 31, rowA0 = tid >> 5;   // A-load mapping
    const int nbB = tid & 63, kB0   = tid >> 6;   // B-load mapping

    float acc[4][4] = {};

    for (int k0 = 0; k0 < CDIM; k0 += 32) {
        #pragma unroll
        for (int rr = 0; rr < 8; ++rr) {
            int row = rowA0 + rr*8;
            As[kkA*65 + row] = X[(size_t)(m0+row)*CDIM + k0 + kkA];
        }
        #pragma unroll
        for (int rr = 0; rr < 8; ++rr) {
            int k = kB0 + rr*4;
            Bs[k*65 + nbB] = W[(size_t)(k0+k)*DDIM + n0 + nbB];
        }
        __syncthreads();
        #pragma unroll
        for (int k = 0; k < 32; ++k) {
            float a0 = As[k*65 + ty*4 + 0];
            float a1 = As[k*65 + ty*4 + 1];
            float a2 = As[k*65 + ty*4 + 2];
            float a3 = As[k*65 + ty*4 + 3];
            float b0 = Bs[k*65 + tx*4 + 0];
            float b1 = Bs[k*65 + tx*4 + 1];
            float b2 = Bs[k*65 + tx*4 + 2];
            float b3 = Bs[k*65 + tx*4 + 3];
            acc[0][0] += a0*b0; acc[0][1] += a0*b1; acc[0][2] += a0*b2; acc[0][3] += a0*b3;
            acc[1][0] += a1*b0; acc[1][1] += a1*b1; acc[1][2] += a1*b2; acc[1][3] += a1*b3;
            acc[2][0] += a2*b0; acc[2][1] += a2*b1; acc[2][2] += a2*b2; acc[2][3] += a2*b3;
            acc[3][0] += a3*b0; acc[3][1] += a3*b1; acc[3][2] += a3*b2; acc[3][3] += a3*b3;
        }
        __syncthreads();
    }

    float bb0 = bias[n0 + tx*4 + 0];
    float bb1 = bias[n0 + tx*4 + 1];
    float bb2 = bias[n0 + tx*4 + 2];
    float bb3 = bias[n0 + tx*4 + 3];
    #pragma unroll
    for (int ii = 0; ii < 4; ++ii) {
        float4 v;
        v.x = acc[ii][0] + bb0;
        v.y = acc[ii][1] + bb1;
        v.z = acc[ii][2] + bb2;
        v.w = acc[ii][3] + bb3;
        *(float4*)&Fout[(size_t)(m0 + ty*4 + ii)*DDIM + n0 + tx*4] = v;
    }
}

// ---------------------------------------------------------------------------
// Pointwise: seg logits + softmax, r = ||Fsim||^2, conf sigmoid.
// One block = 64 points, 256 threads = 64 points x 4 sub-lanes.
// ---------------------------------------------------------------------------
__global__ __launch_bounds__(256)
void pointwise_kernel(const float* __restrict__ Wseg, const float* __restrict__ bseg,
                      const float* __restrict__ Wcl,  const float* __restrict__ bcl,
                      float* __restrict__ o_soft, float* __restrict__ o_logits,
                      float* __restrict__ o_conf, float* __restrict__ o_conflog)
{
    __shared__ float slog[64][52];
    __shared__ float smx[64], sinv[64];

    const int tid = threadIdx.x;
    const int pl  = tid >> 2;     // local point 0..63
    const int sub = tid & 3;      // 0..3
    const int p   = blockIdx.x * 64 + pl;

    const float* fsim  = g_Fsim  + (size_t)p*DDIM;
    const float* fconf = g_Fconf + (size_t)p*DDIM;
    const float* fsem  = g_Fsem  + (size_t)p*DDIM;

    // r and conf partial sums over this sub-lane's 32 k's
    float rs = 0.f, cs = 0.f;
    #pragma unroll 8
    for (int k = sub*32; k < sub*32 + 32; ++k) {
        float fv = fsim[k];
        rs += fv * fv;
        cs += fconf[k] * Wcl[k];
    }
    rs += __shfl_xor_sync(0xffffffffu, rs, 1);
    rs += __shfl_xor_sync(0xffffffffu, rs, 2);
    cs += __shfl_xor_sync(0xffffffffu, cs, 1);
    cs += __shfl_xor_sync(0xffffffffu, cs, 2);
    if (sub == 0) {
        g_r[p] = rs;
        float cl = cs + bcl[0];
        o_conflog[p] = cl;
        o_conf[p]    = 1.0f / (1.0f + expf(-cl));
    }

    // seg logits: g = sub + 4*gi  (13/13/12/12 groups per sub-lane)
    const int ng = (sub < 2) ? 13 : 12;
    float accs[13];
    #pragma unroll
    for (int gi = 0; gi < 13; ++gi) accs[gi] = 0.f;
    for (int k = 0; k < DDIM; ++k) {
        float fv = fsem[k];
        const float* wrow = Wseg + (size_t)k*NGROUP + sub;
        #pragma unroll
        for (int gi = 0; gi < 13; ++gi) {
            if (gi < ng) accs[gi] += fv * wrow[gi*4];
        }
    }
    for (int gi = 0; gi < ng; ++gi) {
        int g = sub + gi*4;
        float l = accs[gi] + bseg[g];
        slog[pl][g] = l;
        o_logits[(size_t)p*NGROUP + g] = l;
    }
    __syncthreads();

    if (sub == 0) {
        float mx = -1e30f;
        for (int g = 0; g < NGROUP; ++g) mx = fmaxf(mx, slog[pl][g]);
        float s = 0.f;
        for (int g = 0; g < NGROUP; ++g) s += expf(slog[pl][g] - mx);
        smx[pl]  = mx;
        sinv[pl] = 1.0f / s;
    }
    __syncthreads();

    float mx = smx[pl], inv = sinv[pl];
    for (int gi = 0; gi < ng; ++gi) {
        int g = sub + gi*4;
        o_soft[(size_t)p*NGROUP + g] = expf(slog[pl][g] - mx) * inv;
    }
}

// ---------------------------------------------------------------------------
// Gram / simmat: out[b,m,n] = max(10*(r[m] - 2*Fsim[m].Fsim[n] + r[n]), 0)
// Symmetric: grid covers upper-triangle tiles only (2080 per batch); each
// block writes its tile and the transposed tile (via smem transpose stage).
// ---------------------------------------------------------------------------
__global__ __launch_bounds__(256)
void gram_kernel(float* __restrict__ out)
{
    __shared__ __align__(16) float smem[64*72];   // reused: As/Bs, then transpose stage
    float* As = smem;               // [32][65]
    float* Bs = smem + 32*65;       // [32][65]  (2*32*65 = 4160 <= 4608)

    const int b = blockIdx.z;
    const int t = blockIdx.x;
    int j = (int)((sqrtf(8.0f*(float)t + 1.0f) - 1.0f) * 0.5f);
    while ((j+1)*(j+2)/2 <= t) ++j;
    while (j*(j+1)/2 > t)      --j;
    const int i  = t - j*(j+1)/2;       // i <= j
    const int m0 = i*64, n0 = j*64;

    const float* Fb = g_Fsim + (size_t)b*NPT*DDIM;
    const float* rb = g_r + b*NPT;

    const int tid = threadIdx.x;
    const int tx = tid & 15, ty = tid >> 4;
    const int kk = tid & 31, row0 = tid >> 5;

    float acc[4][4] = {};

    for (int k0 = 0; k0 < DDIM; k0 += 32) {
        #pragma unroll
        for (int rr = 0; rr < 8; ++rr) {
            int row = row0 + rr*8;
            As[kk*65 + row] = Fb[(size_t)(m0+row)*DDIM + k0 + kk];
            Bs[kk*65 + row] = Fb[(size_t)(n0+row)*DDIM + k0 + kk];
        }
        __syncthreads();
        #pragma unroll
        for (int k = 0; k < 32; ++k) {
            float a0 = As[k*65 + ty*4 + 0];
            float a1 = As[k*65 + ty*4 + 1];
            float a2 = As[k*65 + ty*4 + 2];
            float a3 = As[k*65 + ty*4 + 3];
            float b0 = Bs[k*65 + tx*4 + 0];
            float b1 = Bs[k*65 + tx*4 + 1];
            float b2 = Bs[k*65 + tx*4 + 2];
            float b3 = Bs[k*65 + tx*4 + 3];
            acc[0][0] += a0*b0; acc[0][1] += a0*b1; acc[0][2] += a0*b2; acc[0][3] += a0*b3;
            acc[1][0] += a1*b0; acc[1][1] += a1*b1; acc[1][2] += a1*b2; acc[1][3] += a1*b3;
            acc[2][0] += a2*b0; acc[2][1] += a2*b1; acc[2][2] += a2*b2; acc[2][3] += a2*b3;
            acc[3][0] += a3*b0; acc[3][1] += a3*b1; acc[3][2] += a3*b2; acc[3][3] += a3*b3;
        }
        __syncthreads();
    }

    float rm[4], rn[4];
    #pragma unroll
    for (int ii = 0; ii < 4; ++ii) rm[ii] = rb[m0 + ty*4 + ii];
    #pragma unroll
    for (int jj = 0; jj < 4; ++jj) rn[jj] = rb[n0 + tx*4 + jj];

    #pragma unroll
    for (int ii = 0; ii < 4; ++ii)
        #pragma unroll
        for (int jj = 0; jj < 4; ++jj)
            acc[ii][jj] = fmaxf(10.0f * (rm[ii] - 2.0f*acc[ii][jj] + rn[jj]), 0.0f);

    const size_t base = (size_t)b * NPT * NPT;

    // Direct tile (coalesced float4)
    #pragma unroll
    for (int ii = 0; ii < 4; ++ii) {
        float4 v;
        v.x = acc[ii][0]; v.y = acc[ii][1]; v.z = acc[ii][2]; v.w = acc[ii][3];
        *(float4*)&out[base + (size_t)(m0 + ty*4 + ii)*NPT + n0 + tx*4] = v;
    }

    // Transposed tile (D is symmetric) via smem stage for coalesced writes
    if (i != j) {
        float* Ts = smem;    // [64][72], 16B-aligned rows (72 % 4 == 0)
        #pragma unroll
        for (int ii = 0; ii < 4; ++ii)
            #pragma unroll
            for (int jj = 0; jj < 4; ++jj)
                Ts[(tx*4 + jj)*72 + ty*4 + ii] = acc[ii][jj];
        __syncthreads();
        #pragma unroll
        for (int v = 0; v < 4; ++v) {
            int idx  = tid + v*256;       // 0..1023
            int rrow = idx >> 4;          // 0..63
            int c4   = idx & 15;
            float4 vv = *(float4*)&Ts[rrow*72 + c4*4];
            *(float4*)&out[base + (size_t)(n0 + rrow)*NPT + m0 + c4*4] = vv;
        }
    }
}

// ---------------------------------------------------------------------------
extern "C" void kernel_launch(void* const* d_in, const int* in_sizes, int n_in,
                              void* d_out, int out_size)
{
    const float* X     = (const float*)d_in[0];
    const float* Wsem  = (const float*)d_in[1];
    const float* bsem  = (const float*)d_in[2];
    const float* Wseg  = (const float*)d_in[3];
    const float* bseg  = (const float*)d_in[4];
    const float* Wsim  = (const float*)d_in[5];
    const float* bsim  = (const float*)d_in[6];
    const float* Wconf = (const float*)d_in[7];
    const float* bconf = (const float*)d_in[8];
    const float* Wcl   = (const float*)d_in[9];
    const float* bcl   = (const float*)d_in[10];

    float* out       = (float*)d_out;
    float* o_soft    = out + OFF_SOFT;
    float* o_logits  = out + OFF_LOGITS;
    float* o_sim     = out + OFF_SIM;
    float* o_conf    = out + OFF_CONF;
    float* o_conflog = out + OFF_CONFLOG;

    dim3 gh(BN/64, DDIM/64);   // 256 x 2
    head_gemm<0><<<gh, 256>>>(X, Wsem,  bsem);
    head_gemm<1><<<gh, 256>>>(X, Wsim,  bsim);
    head_gemm<2><<<gh, 256>>>(X, Wconf, bconf);

    pointwise_kernel<<<BN/64, 256>>>(Wseg, bseg, Wcl, bcl,
                                     o_soft, o_logits, o_conf, o_conflog);

    const int ntiles = (NPT/64) * (NPT/64 + 1) / 2;   // 2080
    gram_kernel<<<dim3(ntiles, 1, BATCH), 256>>>(o_sim);
}

// round 6
// speedup vs baseline: 1.9219x; 1.9219x over previous
#include <cuda_runtime.h>
#include <cstdint>

#define BATCH  4
#define NPT    4096
#define CDIM   256
#define DDIM   128
#define NGROUP 50
#define BN     (BATCH*NPT)

#define OFF_SOFT    0
#define OFF_LOGITS  819200
#define OFF_SIM     1638400
#define OFF_CONF    68747264
#define OFF_CONFLOG 68763648

// Scratch (device globals: allocation-free)
__device__ float g_Fsem[BN*DDIM];
__device__ float g_Fsim[BN*DDIM];
__device__ float g_Fconf[BN*DDIM];
__device__ float g_r[BN];

__device__ __forceinline__ uint32_t f2tf32(float f) {
    uint32_t r;
    asm("cvt.rna.tf32.f32 %0, %1;" : "=r"(r) : "f"(f));
    return r;
}

__device__ __forceinline__ void mma_tf32(float c[4],
                                         uint32_t a0, uint32_t a1, uint32_t a2, uint32_t a3,
                                         uint32_t b0, uint32_t b1) {
    asm volatile(
        "mma.sync.aligned.m16n8k8.row.col.f32.tf32.tf32.f32 "
        "{%0,%1,%2,%3}, {%4,%5,%6,%7}, {%8,%9}, {%0,%1,%2,%3};"
        : "+f"(c[0]), "+f"(c[1]), "+f"(c[2]), "+f"(c[3])
        : "r"(a0), "r"(a1), "r"(a2), "r"(a3), "r"(b0), "r"(b1));
}

// ---------------------------------------------------------------------------
// Head GEMM: F = X @ W + b.   X: [BN, 256], W: [256, 128], F: [BN, 128]
// ---------------------------------------------------------------------------
template <int HEAD>
__global__ __launch_bounds__(256)
void head_gemm(const float* __restrict__ X,
               const float* __restrict__ W,
               const float* __restrict__ bias)
{
    float* Fout = (HEAD == 0) ? g_Fsem : (HEAD == 1) ? g_Fsim : g_Fconf;

    __shared__ __align__(16) float As[32*65];
    __shared__ __align__(16) float Bs[32*65];

    const int m0  = blockIdx.x * 64;
    const int n0  = blockIdx.y * 64;
    const int tid = threadIdx.x;
    const int tx  = tid & 15;
    const int ty  = tid >> 4;
    const int kkA = tid & 31, rowA0 = tid >> 5;
    const int nbB = tid & 63, kB0   = tid >> 6;

    float acc[4][4] = {};

    for (int k0 = 0; k0 < CDIM; k0 += 32) {
        #pragma unroll
        for (int rr = 0; rr < 8; ++rr) {
            int row = rowA0 + rr*8;
            As[kkA*65 + row] = X[(size_t)(m0+row)*CDIM + k0 + kkA];
        }
        #pragma unroll
        for (int rr = 0; rr < 8; ++rr) {
            int k = kB0 + rr*4;
            Bs[k*65 + nbB] = W[(size_t)(k0+k)*DDIM + n0 + nbB];
        }
        __syncthreads();
        #pragma unroll
        for (int k = 0; k < 32; ++k) {
            float a0 = As[k*65 + ty*4 + 0];
            float a1 = As[k*65 + ty*4 + 1];
            float a2 = As[k*65 + ty*4 + 2];
            float a3 = As[k*65 + ty*4 + 3];
            float b0 = Bs[k*65 + tx*4 + 0];
            float b1 = Bs[k*65 + tx*4 + 1];
            float b2 = Bs[k*65 + tx*4 + 2];
            float b3 = Bs[k*65 + tx*4 + 3];
            acc[0][0] += a0*b0; acc[0][1] += a0*b1; acc[0][2] += a0*b2; acc[0][3] += a0*b3;
            acc[1][0] += a1*b0; acc[1][1] += a1*b1; acc[1][2] += a1*b2; acc[1][3] += a1*b3;
            acc[2][0] += a2*b0; acc[2][1] += a2*b1; acc[2][2] += a2*b2; acc[2][3] += a2*b3;
            acc[3][0] += a3*b0; acc[3][1] += a3*b1; acc[3][2] += a3*b2; acc[3][3] += a3*b3;
        }
        __syncthreads();
    }

    float bb0 = bias[n0 + tx*4 + 0];
    float bb1 = bias[n0 + tx*4 + 1];
    float bb2 = bias[n0 + tx*4 + 2];
    float bb3 = bias[n0 + tx*4 + 3];
    #pragma unroll
    for (int ii = 0; ii < 4; ++ii) {
        float4 v;
        v.x = acc[ii][0] + bb0;
        v.y = acc[ii][1] + bb1;
        v.z = acc[ii][2] + bb2;
        v.w = acc[ii][3] + bb3;
        *(float4*)&Fout[(size_t)(m0 + ty*4 + ii)*DDIM + n0 + tx*4] = v;
    }
}

// ---------------------------------------------------------------------------
// Pointwise: seg logits + softmax, r = ||Fsim||^2, conf sigmoid.
// Block: 128 points, 256 threads = 64 point-pairs x 4 sub-lanes.
// ---------------------------------------------------------------------------
__global__ __launch_bounds__(256)
void pointwise_kernel(const float* __restrict__ Wseg, const float* __restrict__ bseg,
                      const float* __restrict__ Wcl,  const float* __restrict__ bcl,
                      float* __restrict__ o_soft, float* __restrict__ o_logits,
                      float* __restrict__ o_conf, float* __restrict__ o_conflog)
{
    __shared__ float sW[128*52];

    const int tid = threadIdx.x;
    for (int i = tid; i < 128*NGROUP; i += 256) {
        int k = i / NGROUP, g = i - k*NGROUP;
        sW[k*52 + g] = Wseg[i];
    }

    const int sub = tid & 3;
    const int q   = tid >> 2;             // pair index 0..63
    const int p0  = blockIdx.x*128 + q*2;
    const int p1  = p0 + 1;
    __syncthreads();

    // r = ||Fsim||^2 and conf logits (each sub-lane owns 32 k's)
    {
        const float4* f0 = (const float4*)(g_Fsim  + (size_t)p0*DDIM + sub*32);
        const float4* f1 = (const float4*)(g_Fsim  + (size_t)p1*DDIM + sub*32);
        const float4* c0 = (const float4*)(g_Fconf + (size_t)p0*DDIM + sub*32);
        const float4* c1 = (const float4*)(g_Fconf + (size_t)p1*DDIM + sub*32);
        const float4* wc = (const float4*)(Wcl + sub*32);
        float rs0 = 0.f, rs1 = 0.f, cs0 = 0.f, cs1 = 0.f;
        #pragma unroll
        for (int v = 0; v < 8; ++v) {
            float4 a = f0[v], b = f1[v], x = c0[v], y = c1[v], w = wc[v];
            rs0 += a.x*a.x + a.y*a.y + a.z*a.z + a.w*a.w;
            rs1 += b.x*b.x + b.y*b.y + b.z*b.z + b.w*b.w;
            cs0 += x.x*w.x + x.y*w.y + x.z*w.z + x.w*w.w;
            cs1 += y.x*w.x + y.y*w.y + y.z*w.z + y.w*w.w;
        }
        rs0 += __shfl_xor_sync(0xffffffffu, rs0, 1);
        rs0 += __shfl_xor_sync(0xffffffffu, rs0, 2);
        rs1 += __shfl_xor_sync(0xffffffffu, rs1, 1);
        rs1 += __shfl_xor_sync(0xffffffffu, rs1, 2);
        cs0 += __shfl_xor_sync(0xffffffffu, cs0, 1);
        cs0 += __shfl_xor_sync(0xffffffffu, cs0, 2);
        cs1 += __shfl_xor_sync(0xffffffffu, cs1, 1);
        cs1 += __shfl_xor_sync(0xffffffffu, cs1, 2);
        if (sub == 0) {
            g_r[p0] = rs0;
            g_r[p1] = rs1;
            float bc = bcl[0];
            float cl0 = cs0 + bc, cl1 = cs1 + bc;
            o_conflog[p0] = cl0;
            o_conflog[p1] = cl1;
            o_conf[p0] = 1.0f / (1.0f + expf(-cl0));
            o_conf[p1] = 1.0f / (1.0f + expf(-cl1));
        }
    }

    // seg logits: group g = sub + 4*gi  (13/13/12/12 per sub-lane)
    const int ng = 13 - (sub >> 1);
    float acc0[13], acc1[13];
    #pragma unroll
    for (int gi = 0; gi < 13; ++gi) { acc0[gi] = 0.f; acc1[gi] = 0.f; }

    const float* f0p = g_Fsem + (size_t)p0*DDIM;
    const float* f1p = g_Fsem + (size_t)p1*DDIM;
    for (int k = 0; k < DDIM; ++k) {
        float f0 = __ldg(f0p + k);
        float f1 = __ldg(f1p + k);
        const float* wr = &sW[k*52 + sub];
        #pragma unroll
        for (int gi = 0; gi < 13; ++gi) {
            if (gi < ng) {
                float w = wr[gi*4];
                acc0[gi] += f0*w;
                acc1[gi] += f1*w;
            }
        }
    }

    // bias + max
    float mx0 = -1e30f, mx1 = -1e30f;
    #pragma unroll
    for (int gi = 0; gi < 13; ++gi) {
        if (gi < ng) {
            float bb = bseg[sub + gi*4];
            acc0[gi] += bb;  acc1[gi] += bb;
            mx0 = fmaxf(mx0, acc0[gi]);
            mx1 = fmaxf(mx1, acc1[gi]);
        }
    }
    mx0 = fmaxf(mx0, __shfl_xor_sync(0xffffffffu, mx0, 1));
    mx0 = fmaxf(mx0, __shfl_xor_sync(0xffffffffu, mx0, 2));
    mx1 = fmaxf(mx1, __shfl_xor_sync(0xffffffffu, mx1, 1));
    mx1 = fmaxf(mx1, __shfl_xor_sync(0xffffffffu, mx1, 2));

    float s0 = 0.f, s1 = 0.f;
    float e0[13], e1[13];
    #pragma unroll
    for (int gi = 0; gi < 13; ++gi) {
        if (gi < ng) {
            e0[gi] = expf(acc0[gi] - mx0);  s0 += e0[gi];
            e1[gi] = expf(acc1[gi] - mx1);  s1 += e1[gi];
        }
    }
    s0 += __shfl_xor_sync(0xffffffffu, s0, 1);
    s0 += __shfl_xor_sync(0xffffffffu, s0, 2);
    s1 += __shfl_xor_sync(0xffffffffu, s1, 1);
    s1 += __shfl_xor_sync(0xffffffffu, s1, 2);
    float i0 = 1.0f / s0, i1 = 1.0f / s1;

    #pragma unroll
    for (int gi = 0; gi < 13; ++gi) {
        if (gi < ng) {
            int g = sub + gi*4;
            o_logits[(size_t)p0*NGROUP + g] = acc0[gi];
            o_logits[(size_t)p1*NGROUP + g] = acc1[gi];
            o_soft[(size_t)p0*NGROUP + g]   = e0[gi]*i0;
            o_soft[(size_t)p1*NGROUP + g]   = e1[gi]*i1;
        }
    }
}

// ---------------------------------------------------------------------------
// Gram / simmat via mma.sync tf32 (legacy tensor path, valid on compute_103).
//   out[b,m,n] = max(10*(r[m] - 2*Fsim[m].Fsim[n] + r[n]), 0)
// 128x128 tile per CTA, triangular grid; 8 warps = 4(m) x 2(n); each warp
// 32x64 via 2x8 m16n8k8 fragments. K chunked by 32 with register prefetch.
//
// SMEM tf32 layout (per 32-k chunk): word(row, kl) = chl*1026 + row*8 + tg*2 + half
//   where chl = kl>>3, tg = kl&3, half = (kl>>2)&1.
// -> every A/B fragment pair {k=tg, k=tg+4} is one aligned, conflict-free LDS.64.
// ---------------------------------------------------------------------------
#define GTILE 128
#define CHSTR 1026            // chl stride in words (1024 + 2: de-conflicts stores)

__global__ __launch_bounds__(256)
void gram_mma(float* __restrict__ out)
{
    __shared__ __align__(16) uint32_t smem_u[8320];   // A(4104) + B(4104) <= 8320; Ts aliases
    __shared__ float rm_s[GTILE], rn_s[GTILE];

    uint32_t* sA = smem_u;
    uint32_t* sB = smem_u + 4104;
    float*    Ts = (float*)smem_u;                     // [128][65] epilogue stage

    const int b = blockIdx.z;
    const int t = blockIdx.x;
    int j = (int)((sqrtf(8.0f*(float)t + 1.0f) - 1.0f) * 0.5f);
    while ((j+1)*(j+2)/2 <= t) ++j;
    while (j*(j+1)/2 > t)      --j;
    const int i  = t - j*(j+1)/2;       // i <= j
    const int m0 = i*GTILE, n0 = j*GTILE;
    const bool diag = (i == j);

    const float* Fb = g_Fsim + (size_t)b*NPT*DDIM;
    const float* rb = g_r + b*NPT;

    const int tid  = threadIdx.x;
    const int lane = tid & 31;
    const int w    = tid >> 5;
    const int gID  = lane >> 2;
    const int tg   = lane & 3;
    const int wm   = w & 3;            // warp m: rows wm*32 .. +31
    const int wn   = w >> 2;           // warp n: cols wn*64 .. +63

    if (tid < GTILE) {
        rm_s[tid] = rb[m0 + tid];
        rn_s[tid] = rb[n0 + tid];
    }

    float c[2][8][4];
    #pragma unroll
    for (int mt = 0; mt < 2; ++mt)
        #pragma unroll
        for (int nt = 0; nt < 8; ++nt)
            #pragma unroll
            for (int rr = 0; rr < 4; ++rr) c[mt][nt][rr] = 0.f;

    // per-chunk load assignment: float4 index f = tid + 256*it
    const int frow = tid >> 3;          // base row for it=0 (f>>3 when f<256)
    // general: row = (tid + 256*it) >> 3 = frow + 32*it ; q = tid & 7
    const int q    = tid & 7;
    const int chl0 = q >> 1, half0 = q & 1;
    const int sbase = chl0*CHSTR + half0;   // + row*8 per it

    float4 pa[4], pb[4];
    #pragma unroll
    for (int it = 0; it < 4; ++it) {
        int row = frow + 32*it;
        pa[it] = *(const float4*)&Fb[(size_t)(m0+row)*DDIM + q*4];
        if (!diag)
            pb[it] = *(const float4*)&Fb[(size_t)(n0+row)*DDIM + q*4];
    }

    const uint32_t* sBr = diag ? sA : sB;

    for (int ch = 0; ch < 4; ++ch) {
        // store prefetched chunk (fp32 -> tf32) into fragment-native layout
        #pragma unroll
        for (int it = 0; it < 4; ++it) {
            int row = frow + 32*it;
            int bw  = sbase + row*8;
            sA[bw + 0] = f2tf32(pa[it].x);
            sA[bw + 2] = f2tf32(pa[it].y);
            sA[bw + 4] = f2tf32(pa[it].z);
            sA[bw + 6] = f2tf32(pa[it].w);
            if (!diag) {
                sB[bw + 0] = f2tf32(pb[it].x);
                sB[bw + 2] = f2tf32(pb[it].y);
                sB[bw + 4] = f2tf32(pb[it].z);
                sB[bw + 6] = f2tf32(pb[it].w);
            }
        }
        __syncthreads();

        // prefetch next chunk while computing this one
        if (ch < 3) {
            #pragma unroll
            for (int it = 0; it < 4; ++it) {
                int row = frow + 32*it;
                pa[it] = *(const float4*)&Fb[(size_t)(m0+row)*DDIM + (ch+1)*32 + q*4];
                if (!diag)
                    pb[it] = *(const float4*)&Fb[(size_t)(n0+row)*DDIM + (ch+1)*32 + q*4];
            }
        }

        // 4 k8-steps per chunk
        #pragma unroll
        for (int chl = 0; chl < 4; ++chl) {
            uint32_t a[2][4];
            #pragma unroll
            for (int mt = 0; mt < 2; ++mt) {
                int r0 = wm*32 + mt*16 + gID;
                int ad = chl*CHSTR + r0*8 + tg*2;
                uint2 p0 = *(const uint2*)(sA + ad);        // {a0, a2}
                uint2 p1 = *(const uint2*)(sA + ad + 64);   // {a1, a3} (row+8)
                a[mt][0] = p0.x; a[mt][2] = p0.y;
                a[mt][1] = p1.x; a[mt][3] = p1.y;
            }
            #pragma unroll
            for (int nt = 0; nt < 8; ++nt) {
                int n  = wn*64 + nt*8 + gID;
                int bd = chl*CHSTR + n*8 + tg*2;
                uint2 bp = *(const uint2*)(sBr + bd);       // {b0, b1}
                mma_tf32(c[0][nt], a[0][0], a[0][1], a[0][2], a[0][3], bp.x, bp.y);
                mma_tf32(c[1][nt], a[1][0], a[1][1], a[1][2], a[1][3], bp.x, bp.y);
            }
        }
        __syncthreads();
    }

    // Epilogue: two column-halves through smem stage (Ts aliases sA/sB).
    const size_t base = (size_t)b * NPT * NPT;

    #pragma unroll
    for (int h = 0; h < 2; ++h) {
        if (wn == h) {
            #pragma unroll
            for (int mt = 0; mt < 2; ++mt) {
                int r0 = wm*32 + mt*16 + gID;
                float rm0 = rm_s[r0], rm1 = rm_s[r0 + 8];
                #pragma unroll
                for (int nt = 0; nt < 8; ++nt) {
                    int c0l = nt*8 + tg*2;          // local col 0..63
                    int gc0 = h*64 + c0l;           // tile col 0..127
                    float rn0 = rn_s[gc0], rn1 = rn_s[gc0 + 1];
                    float d00 = fmaxf(10.0f*(rm0 + rn0 - 2.0f*c[mt][nt][0]), 0.0f);
                    float d01 = fmaxf(10.0f*(rm0 + rn1 - 2.0f*c[mt][nt][1]), 0.0f);
                    float d10 = fmaxf(10.0f*(rm1 + rn0 - 2.0f*c[mt][nt][2]), 0.0f);
                    float d11 = fmaxf(10.0f*(rm1 + rn1 - 2.0f*c[mt][nt][3]), 0.0f);
                    if (diag) {
                        if (r0   == gc0)   d00 = 0.0f;
                        if (r0   == gc0+1) d01 = 0.0f;
                        if (r0+8 == gc0)   d10 = 0.0f;
                        if (r0+8 == gc0+1) d11 = 0.0f;
                    }
                    Ts[ r0   *65 + c0l    ] = d00;
                    Ts[ r0   *65 + c0l + 1] = d01;
                    Ts[(r0+8)*65 + c0l    ] = d10;
                    Ts[(r0+8)*65 + c0l + 1] = d11;
                }
            }
        }
        __syncthreads();

        // direct tile half: rows m0..+127, cols n0+h*64..+63 (coalesced)
        #pragma unroll 4
        for (int it = 0; it < 32; ++it) {
            int idx = tid + it*256;
            int row = idx >> 6, cc = idx & 63;
            out[base + (size_t)(m0+row)*NPT + n0 + h*64 + cc] = Ts[row*65 + cc];
        }
        // transposed tile half (symmetry): rows n0+h*64..+63, cols m0..+127
        if (!diag) {
            #pragma unroll 4
            for (int it = 0; it < 32; ++it) {
                int idx = tid + it*256;
                int cc = idx >> 7, row = idx & 127;
                out[base + (size_t)(n0 + h*64 + cc)*NPT + m0 + row] = Ts[row*65 + cc];
            }
        }
        __syncthreads();
    }
}

// ---------------------------------------------------------------------------
extern "C" void kernel_launch(void* const* d_in, const int* in_sizes, int n_in,
                              void* d_out, int out_size)
{
    const float* X     = (const float*)d_in[0];
    const float* Wsem  = (const float*)d_in[1];
    const float* bsem  = (const float*)d_in[2];
    const float* Wseg  = (const float*)d_in[3];
    const float* bseg  = (const float*)d_in[4];
    const float* Wsim  = (const float*)d_in[5];
    const float* bsim  = (const float*)d_in[6];
    const float* Wconf = (const float*)d_in[7];
    const float* bconf = (const float*)d_in[8];
    const float* Wcl   = (const float*)d_in[9];
    const float* bcl   = (const float*)d_in[10];

    float* out       = (float*)d_out;
    float* o_soft    = out + OFF_SOFT;
    float* o_logits  = out + OFF_LOGITS;
    float* o_sim     = out + OFF_SIM;
    float* o_conf    = out + OFF_CONF;
    float* o_conflog = out + OFF_CONFLOG;

    dim3 gh(BN/64, DDIM/64);   // 256 x 2
    head_gemm<0><<<gh, 256>>>(X, Wsem,  bsem);
    head_gemm<1><<<gh, 256>>>(X, Wsim,  bsim);
    head_gemm<2><<<gh, 256>>>(X, Wconf, bconf);

    pointwise_kernel<<<BN/128, 256>>>(Wseg, bseg, Wcl, bcl,
                                      o_soft, o_logits, o_conf, o_conflog);

    const int ntiles = (NPT/GTILE) * (NPT/GTILE + 1) / 2;   // 528
    gram_mma<<<dim3(ntiles, 1, BATCH), 256>>>(o_sim);
}

// round 7
// speedup vs baseline: 3.4418x; 1.7908x over previous
#include <cuda_runtime.h>
#include <cuda_fp16.h>
#include <cstdint>

#define BATCH  4
#define NPT    4096
#define CDIM   256
#define DDIM   128
#define NGROUP 50
#define BN     (BATCH*NPT)

#define OFF_SOFT    0
#define OFF_LOGITS  819200
#define OFF_SIM     1638400
#define OFF_CONF    68747264
#define OFF_CONFLOG 68763648

// Scratch (device globals: allocation-free)
__device__ float   g_Fsem[BN*DDIM];
__device__ float   g_Fconf[BN*DDIM];
__device__ __half2 g_FsimH[BN*DDIM/2];     // fp16 Fsim, row-major k-pairs
__device__ __half2 g_XH[BN*CDIM/2];        // fp16 X, row-major k-pairs
__device__ __half2 g_WH[3*DDIM*CDIM/2];    // [head][n][kw] = {W[2kw][n], W[2kw+1][n]}
__device__ float   g_r[BN];

#define CHSTR 1026   // words per k16-chunk in smem frag layout (1024 + 2 pad)

__device__ __forceinline__ void mma_f16(float c[4],
                                        uint32_t a0, uint32_t a1, uint32_t a2, uint32_t a3,
                                        uint32_t b0, uint32_t b1) {
    asm volatile(
        "mma.sync.aligned.m16n8k16.row.col.f32.f16.f16.f32 "
        "{%0,%1,%2,%3}, {%4,%5,%6,%7}, {%8,%9}, {%0,%1,%2,%3};"
        : "+f"(c[0]), "+f"(c[1]), "+f"(c[2]), "+f"(c[3])
        : "r"(a0), "r"(a1), "r"(a2), "r"(a3), "r"(b0), "r"(b1));
}

// ---------------------------------------------------------------------------
// prep kernels: pack X and W into fp16 layouts
// ---------------------------------------------------------------------------
__global__ __launch_bounds__(256) void prep_x(const float* __restrict__ X)
{
    int i = (blockIdx.x*256 + threadIdx.x)*4;   // BN*CDIM total, /4 per thread
    float4 v = *(const float4*)(X + i);
    g_XH[(i>>1) + 0] = __floats2half2_rn(v.x, v.y);
    g_XH[(i>>1) + 1] = __floats2half2_rn(v.z, v.w);
}

__global__ __launch_bounds__(256) void prep_w(const float* __restrict__ W0,
                                              const float* __restrict__ W1,
                                              const float* __restrict__ W2)
{
    int idx = blockIdx.x*256 + threadIdx.x;     // 0..49151
    int head = idx >> 14;
    int r    = idx & 16383;
    int n    = r >> 7;
    int kw   = r & 127;
    const float* W = (head == 0) ? W0 : (head == 1) ? W1 : W2;
    g_WH[idx] = __floats2half2_rn(W[(2*kw)*DDIM + n], W[(2*kw+1)*DDIM + n]);
}

// ---------------------------------------------------------------------------
// Fused head GEMMs: F = X @ W + b via fp16 mma.  Grid: (BN/128, 3 heads).
// 8 warps = 4(m) x 2(n); warp tile 32x64; K = 256 in 4 k64 stages.
// head 0 -> g_Fsem (fp32), head 1 -> g_FsimH (fp16 only), head 2 -> g_Fconf.
// ---------------------------------------------------------------------------
__global__ __launch_bounds__(256)
void heads_mma(const float* __restrict__ bias0,
               const float* __restrict__ bias1,
               const float* __restrict__ bias2)
{
    __shared__ __align__(16) uint32_t smem_u[8320];  // sA(4104)+sB(4104)->8320 alias Ts
    uint32_t* sA = smem_u;
    uint32_t* sB = smem_u + 4104;
    float*    Ts = (float*)smem_u;                   // [128][65]

    const int head = blockIdx.y;
    const int m0   = blockIdx.x * 128;
    const float* bias = (head == 0) ? bias0 : (head == 1) ? bias1 : bias2;

    const int tid  = threadIdx.x;
    const int lane = tid & 31;
    const int w    = tid >> 5;
    const int gID  = lane >> 2;
    const int tg   = lane & 3;
    const int wm   = w & 3;
    const int wn   = w >> 2;

    const uint4* XA = (const uint4*)g_XH;                    // row stride 32 uint4
    const uint4* WB = (const uint4*)g_WH + head*4096;        // row stride 32 uint4

    float c[2][8][4];
    #pragma unroll
    for (int mt = 0; mt < 2; ++mt)
        #pragma unroll
        for (int nt = 0; nt < 8; ++nt)
            #pragma unroll
            for (int rr = 0; rr < 4; ++rr) c[mt][nt][rr] = 0.f;

    for (int st = 0; st < 4; ++st) {
        __syncthreads();
        #pragma unroll
        for (int it = 0; it < 4; ++it) {
            int u   = tid + it*256;
            int row = u >> 3;
            int g4  = u & 7;
            int chl = g4 >> 1, kw4 = g4 & 1;
            uint4 va = XA[(size_t)(m0+row)*32 + st*8 + g4];
            uint4 vb = WB[(size_t)row*32 + st*8 + g4];
            int base = chl*CHSTR + row*8 + kw4;
            sA[base+0] = va.x; sA[base+2] = va.y; sA[base+4] = va.z; sA[base+6] = va.w;
            sB[base+0] = vb.x; sB[base+2] = vb.y; sB[base+4] = vb.z; sB[base+6] = vb.w;
        }
        __syncthreads();

        #pragma unroll
        for (int chl = 0; chl < 4; ++chl) {
            uint32_t a[2][4];
            #pragma unroll
            for (int mt = 0; mt < 2; ++mt) {
                int r0 = wm*32 + mt*16 + gID;
                int ad = chl*CHSTR + r0*8 + tg*2;
                uint2 p0 = *(const uint2*)(sA + ad);        // {a0,a2}
                uint2 p1 = *(const uint2*)(sA + ad + 64);   // {a1,a3}
                a[mt][0] = p0.x; a[mt][2] = p0.y;
                a[mt][1] = p1.x; a[mt][3] = p1.y;
            }
            #pragma unroll
            for (int nt = 0; nt < 8; ++nt) {
                int n  = wn*64 + nt*8 + gID;
                int bd = chl*CHSTR + n*8 + tg*2;
                uint2 bp = *(const uint2*)(sB + bd);        // {b0,b1}
                mma_f16(c[0][nt], a[0][0], a[0][1], a[0][2], a[0][3], bp.x, bp.y);
                mma_f16(c[1][nt], a[1][0], a[1][1], a[1][2], a[1][3], bp.x, bp.y);
            }
        }
    }
    __syncthreads();

    // Epilogue: bias + store, two column-halves through Ts
    float* Fout = (head == 0) ? g_Fsem : g_Fconf;   // head 1 never uses Fout

    #pragma unroll
    for (int h = 0; h < 2; ++h) {
        if (wn == h) {
            #pragma unroll
            for (int mt = 0; mt < 2; ++mt) {
                int r0 = wm*32 + mt*16 + gID;
                #pragma unroll
                for (int nt = 0; nt < 8; ++nt) {
                    int c0l = nt*8 + tg*2;
                    int gc  = h*64 + c0l;
                    float b0 = bias[gc], b1 = bias[gc+1];
                    Ts[ r0   *65 + c0l    ] = c[mt][nt][0] + b0;
                    Ts[ r0   *65 + c0l + 1] = c[mt][nt][1] + b1;
                    Ts[(r0+8)*65 + c0l    ] = c[mt][nt][2] + b0;
                    Ts[(r0+8)*65 + c0l + 1] = c[mt][nt][3] + b1;
                }
            }
        }
        __syncthreads();

        if (head == 1) {
            #pragma unroll
            for (int it = 0; it < 16; ++it) {
                int u   = tid + it*256;          // 0..4095 = 128 rows x 32 half2
                int row = u >> 5;
                int c2  = u & 31;
                __half2 hv = __floats2half2_rn(Ts[row*65 + c2*2], Ts[row*65 + c2*2 + 1]);
                g_FsimH[(size_t)(m0+row)*64 + h*32 + c2] = hv;
            }
        } else {
            #pragma unroll
            for (int it = 0; it < 32; ++it) {
                int idx = tid + it*256;          // 0..8191 = 128 rows x 64 cols
                int row = idx >> 6;
                int cc  = idx & 63;
                Fout[(size_t)(m0+row)*DDIM + h*64 + cc] = Ts[row*65 + cc];
            }
        }
        __syncthreads();
    }
}

// ---------------------------------------------------------------------------
// Pointwise: seg logits + softmax, r = ||FsimH||^2, conf sigmoid.
// 64 points per block (256 blocks), 256 threads = 64 points x 4 sub-lanes.
// Contiguous group ownership per sub: bases {0,13,26,38}, counts {13,13,12,12}.
// Wseg staged per-sub padded: sW[sub*2052 + k*16 + gi] for LDS.128.
// ---------------------------------------------------------------------------
__global__ __launch_bounds__(256)
void pointwise_kernel(const float* __restrict__ Wseg, const float* __restrict__ bseg,
                      const float* __restrict__ Wcl,  const float* __restrict__ bcl,
                      float* __restrict__ o_soft, float* __restrict__ o_logits,
                      float* __restrict__ o_conf, float* __restrict__ o_conflog)
{
    __shared__ __align__(16) float sW[3*2052 + 2048];   // 8204 words

    const int tid = threadIdx.x;
    for (int i = tid; i < DDIM*NGROUP; i += 256) {
        int k = i / NGROUP, g = i - k*NGROUP;
        int sb = (g >= 13) + (g >= 26) + (g >= 38);
        int gb = sb*13 - (sb == 3 ? 1 : 0);
        sW[sb*2052 + k*16 + (g - gb)] = Wseg[i];
    }

    const int sub = tid & 3;
    const int q   = tid >> 2;                 // point 0..63
    const int p   = blockIdx.x*64 + q;
    __syncthreads();

    // r (from fp16 Fsim — consistent with gram) and conf logits
    {
        const uint4*  fh = (const uint4*)g_FsimH + (size_t)p*16 + sub*4;
        const float4* fc = (const float4*)(g_Fconf + (size_t)p*DDIM + sub*32);
        const float4* wc = (const float4*)(Wcl + sub*32);
        float rs = 0.f, cs = 0.f;
        #pragma unroll
        for (int v = 0; v < 4; ++v) {
            uint4 hv = fh[v];
            float2 f0 = __half22float2(*(__half2*)&hv.x);
            float2 f1 = __half22float2(*(__half2*)&hv.y);
            float2 f2 = __half22float2(*(__half2*)&hv.z);
            float2 f3 = __half22float2(*(__half2*)&hv.w);
            rs += f0.x*f0.x + f0.y*f0.y + f1.x*f1.x + f1.y*f1.y
                + f2.x*f2.x + f2.y*f2.y + f3.x*f3.x + f3.y*f3.y;
        }
        #pragma unroll
        for (int v = 0; v < 8; ++v) {
            float4 x = fc[v], ww = wc[v];
            cs += x.x*ww.x + x.y*ww.y + x.z*ww.z + x.w*ww.w;
        }
        rs += __shfl_xor_sync(0xffffffffu, rs, 1);
        rs += __shfl_xor_sync(0xffffffffu, rs, 2);
        cs += __shfl_xor_sync(0xffffffffu, cs, 1);
        cs += __shfl_xor_sync(0xffffffffu, cs, 2);
        if (sub == 0) {
            g_r[p] = rs;
            float cl = cs + bcl[0];
            o_conflog[p] = cl;
            o_conf[p]    = 1.0f / (1.0f + expf(-cl));
        }
    }

    // seg logits
    const int ng = 13 - (sub >> 1);
    const int gb = sub*13 - (sub == 3 ? 1 : 0);
    float acc[13];
    #pragma unroll
    for (int gi = 0; gi < 13; ++gi) acc[gi] = 0.f;

    const float* fp = g_Fsem + (size_t)p*DDIM;
    const int sbase = sub*2052;
    for (int k0 = 0; k0 < DDIM; k0 += 4) {
        float4 f = *(const float4*)(fp + k0);
        #pragma unroll
        for (int dk = 0; dk < 4; ++dk) {
            float fv = (dk == 0) ? f.x : (dk == 1) ? f.y : (dk == 2) ? f.z : f.w;
            const float* wr = &sW[sbase + (k0+dk)*16];
            float4 w0 = *(const float4*)(wr + 0);
            float4 w1 = *(const float4*)(wr + 4);
            float4 w2 = *(const float4*)(wr + 8);
            acc[0] += fv*w0.x; acc[1] += fv*w0.y; acc[2]  += fv*w0.z; acc[3]  += fv*w0.w;
            acc[4] += fv*w1.x; acc[5] += fv*w1.y; acc[6]  += fv*w1.z; acc[7]  += fv*w1.w;
            acc[8] += fv*w2.x; acc[9] += fv*w2.y; acc[10] += fv*w2.z; acc[11] += fv*w2.w;
            if (ng == 13) acc[12] += fv*wr[12];
        }
    }

    float mx = -1e30f;
    #pragma unroll
    for (int gi = 0; gi < 13; ++gi) {
        if (gi < ng) {
            acc[gi] += bseg[gb + gi];
            mx = fmaxf(mx, acc[gi]);
        }
    }
    mx = fmaxf(mx, __shfl_xor_sync(0xffffffffu, mx, 1));
    mx = fmaxf(mx, __shfl_xor_sync(0xffffffffu, mx, 2));

    float s = 0.f, ex[13];
    #pragma unroll
    for (int gi = 0; gi < 13; ++gi) {
        if (gi < ng) { ex[gi] = expf(acc[gi] - mx); s += ex[gi]; }
    }
    s += __shfl_xor_sync(0xffffffffu, s, 1);
    s += __shfl_xor_sync(0xffffffffu, s, 2);
    float inv = 1.0f / s;

    #pragma unroll
    for (int gi = 0; gi < 13; ++gi) {
        if (gi < ng) {
            int g = gb + gi;
            o_logits[(size_t)p*NGROUP + g] = acc[gi];
            o_soft[(size_t)p*NGROUP + g]   = ex[gi]*inv;
        }
    }
}

// ---------------------------------------------------------------------------
// Gram / simmat via fp16 mma: 128x128 tiles, triangular grid, symmetric write.
//   out[b,m,n] = max(10*(r[m] - 2*FsimH[m].FsimH[n] + r[n]), 0)
// ---------------------------------------------------------------------------
#define GTILE 128

__global__ __launch_bounds__(256)
void gram_mma(float* __restrict__ out)
{
    __shared__ __align__(16) uint32_t smem_u[8320];   // sA(4104)+sB(4104); Ts alias
    __shared__ float rm_s[GTILE], rn_s[GTILE];

    uint32_t* sA = smem_u;
    uint32_t* sB = smem_u + 4104;
    float*    Ts = (float*)smem_u;                    // [128][65]

    const int b = blockIdx.z;
    const int t = blockIdx.x;
    int j = (int)((sqrtf(8.0f*(float)t + 1.0f) - 1.0f) * 0.5f);
    while ((j+1)*(j+2)/2 <= t) ++j;
    while (j*(j+1)/2 > t)      --j;
    const int i  = t - j*(j+1)/2;       // i <= j
    const int m0 = i*GTILE, n0 = j*GTILE;
    const bool diag = (i == j);

    const uint4* FH = (const uint4*)g_FsimH + (size_t)b*NPT*16;  // row = 16 uint4
    const float* rb = g_r + b*NPT;

    const int tid  = threadIdx.x;
    const int lane = tid & 31;
    const int w    = tid >> 5;
    const int gID  = lane >> 2;
    const int tg   = lane & 3;
    const int wm   = w & 3;
    const int wn   = w >> 2;

    if (tid < GTILE) {
        rm_s[tid] = rb[m0 + tid];
        rn_s[tid] = rb[n0 + tid];
    }

    float c[2][8][4];
    #pragma unroll
    for (int mt = 0; mt < 2; ++mt)
        #pragma unroll
        for (int nt = 0; nt < 8; ++nt)
            #pragma unroll
            for (int rr = 0; rr < 4; ++rr) c[mt][nt][rr] = 0.f;

    const uint32_t* sBr = diag ? sA : sB;

    for (int st = 0; st < 2; ++st) {
        __syncthreads();
        #pragma unroll
        for (int it = 0; it < 4; ++it) {
            int u   = tid + it*256;
            int row = u >> 3;
            int g4  = u & 7;
            int chl = g4 >> 1, kw4 = g4 & 1;
            int base = chl*CHSTR + row*8 + kw4;
            uint4 va = FH[(size_t)(m0+row)*16 + st*8 + g4];
            sA[base+0] = va.x; sA[base+2] = va.y; sA[base+4] = va.z; sA[base+6] = va.w;
            if (!diag) {
                uint4 vb = FH[(size_t)(n0+row)*16 + st*8 + g4];
                sB[base+0] = vb.x; sB[base+2] = vb.y; sB[base+4] = vb.z; sB[base+6] = vb.w;
            }
        }
        __syncthreads();

        #pragma unroll
        for (int chl = 0; chl < 4; ++chl) {
            uint32_t a[2][4];
            #pragma unroll
            for (int mt = 0; mt < 2; ++mt) {
                int r0 = wm*32 + mt*16 + gID;
                int ad = chl*CHSTR + r0*8 + tg*2;
                uint2 p0 = *(const uint2*)(sA + ad);
                uint2 p1 = *(const uint2*)(sA + ad + 64);
                a[mt][0] = p0.x; a[mt][2] = p0.y;
                a[mt][1] = p1.x; a[mt][3] = p1.y;
            }
            #pragma unroll
            for (int nt = 0; nt < 8; ++nt) {
                int n  = wn*64 + nt*8 + gID;
                int bd = chl*CHSTR + n*8 + tg*2;
                uint2 bp = *(const uint2*)(sBr + bd);
                mma_f16(c[0][nt], a[0][0], a[0][1], a[0][2], a[0][3], bp.x, bp.y);
                mma_f16(c[1][nt], a[1][0], a[1][1], a[1][2], a[1][3], bp.x, bp.y);
            }
        }
    }
    __syncthreads();

    // Epilogue: two column-halves through smem stage
    const size_t base = (size_t)b * NPT * NPT;

    #pragma unroll
    for (int h = 0; h < 2; ++h) {
        if (wn == h) {
            #pragma unroll
            for (int mt = 0; mt < 2; ++mt) {
                int r0 = wm*32 + mt*16 + gID;
                float rm0 = rm_s[r0], rm1 = rm_s[r0 + 8];
                #pragma unroll
                for (int nt = 0; nt < 8; ++nt) {
                    int c0l = nt*8 + tg*2;
                    int gc0 = h*64 + c0l;
                    float rn0 = rn_s[gc0], rn1 = rn_s[gc0 + 1];
                    float d00 = fmaxf(10.0f*(rm0 + rn0 - 2.0f*c[mt][nt][0]), 0.0f);
                    float d01 = fmaxf(10.0f*(rm0 + rn1 - 2.0f*c[mt][nt][1]), 0.0f);
                    float d10 = fmaxf(10.0f*(rm1 + rn0 - 2.0f*c[mt][nt][2]), 0.0f);
                    float d11 = fmaxf(10.0f*(rm1 + rn1 - 2.0f*c[mt][nt][3]), 0.0f);
                    if (diag) {
                        if (r0   == gc0)   d00 = 0.0f;
                        if (r0   == gc0+1) d01 = 0.0f;
                        if (r0+8 == gc0)   d10 = 0.0f;
                        if (r0+8 == gc0+1) d11 = 0.0f;
                    }
                    Ts[ r0   *65 + c0l    ] = d00;
                    Ts[ r0   *65 + c0l + 1] = d01;
                    Ts[(r0+8)*65 + c0l    ] = d10;
                    Ts[(r0+8)*65 + c0l + 1] = d11;
                }
            }
        }
        __syncthreads();

        #pragma unroll 4
        for (int it = 0; it < 32; ++it) {
            int idx = tid + it*256;
            int row = idx >> 6, cc = idx & 63;
            out[base + (size_t)(m0+row)*NPT + n0 + h*64 + cc] = Ts[row*65 + cc];
        }
        if (!diag) {
            #pragma unroll 4
            for (int it = 0; it < 32; ++it) {
                int idx = tid + it*256;
                int cc = idx >> 7, row = idx & 127;
                out[base + (size_t)(n0 + h*64 + cc)*NPT + m0 + row] = Ts[row*65 + cc];
            }
        }
        __syncthreads();
    }
}

// ---------------------------------------------------------------------------
extern "C" void kernel_launch(void* const* d_in, const int* in_sizes, int n_in,
                              void* d_out, int out_size)
{
    const float* X     = (const float*)d_in[0];
    const float* Wsem  = (const float*)d_in[1];
    const float* bsem  = (const float*)d_in[2];
    const float* Wseg  = (const float*)d_in[3];
    const float* bseg  = (const float*)d_in[4];
    const float* Wsim  = (const float*)d_in[5];
    const float* bsim  = (const float*)d_in[6];
    const float* Wconf = (const float*)d_in[7];
    const float* bconf = (const float*)d_in[8];
    const float* Wcl   = (const float*)d_in[9];
    const float* bcl   = (const float*)d_in[10];

    float* out       = (float*)d_out;
    float* o_soft    = out + OFF_SOFT;
    float* o_logits  = out + OFF_LOGITS;
    float* o_sim     = out + OFF_SIM;
    float* o_conf    = out + OFF_CONF;
    float* o_conflog = out + OFF_CONFLOG;

    prep_x<<<BN*CDIM/1024, 256>>>(X);
    prep_w<<<192, 256>>>(Wsem, Wsim, Wconf);

    heads_mma<<<dim3(BN/128, 3), 256>>>(bsem, bsim, bconf);

    pointwise_kernel<<<BN/64, 256>>>(Wseg, bseg, Wcl, bcl,
                                     o_soft, o_logits, o_conf, o_conflog);

    const int ntiles = (NPT/GTILE) * (NPT/GTILE + 1) / 2;   // 528
    gram_mma<<<dim3(ntiles, 1, BATCH), 256>>>(o_sim);
}

// round 8
// speedup vs baseline: 4.2543x; 1.2361x over previous
#include <cuda_runtime.h>
#include <cuda_fp16.h>
#include <cstdint>

#define BATCH  4
#define NPT    4096
#define CDIM   256
#define DDIM   128
#define NGROUP 50
#define BN     (BATCH*NPT)

#define OFF_SOFT    0
#define OFF_LOGITS  819200
#define OFF_SIM     1638400
#define OFF_CONF    68747264
#define OFF_CONFLOG 68763648

// Scratch (device globals: allocation-free)
__device__ __half2 g_FsimH[BN*DDIM/2];     // fp16 Fsim, row-major k-pairs
__device__ __half2 g_XH[BN*CDIM/2];        // fp16 X, row-major k-pairs
__device__ __half2 g_WH[3*DDIM*CDIM/2];    // [head][n][kw] = {W[2kw][n], W[2kw+1][n]}
__device__ float   g_r[BN];

#define CHSTR 1026   // words per k16-chunk in smem frag layout (1024 + 2 pad)

__device__ __forceinline__ void mma_f16(float c[4],
                                        uint32_t a0, uint32_t a1, uint32_t a2, uint32_t a3,
                                        uint32_t b0, uint32_t b1) {
    asm volatile(
        "mma.sync.aligned.m16n8k16.row.col.f32.f16.f16.f32 "
        "{%0,%1,%2,%3}, {%4,%5,%6,%7}, {%8,%9}, {%0,%1,%2,%3};"
        : "+f"(c[0]), "+f"(c[1]), "+f"(c[2]), "+f"(c[3])
        : "r"(a0), "r"(a1), "r"(a2), "r"(a3), "r"(b0), "r"(b1));
}

// ---------------------------------------------------------------------------
// prep kernels: pack X and W into fp16 layouts
// ---------------------------------------------------------------------------
__global__ __launch_bounds__(256) void prep_x(const float* __restrict__ X)
{
    int i = (blockIdx.x*256 + threadIdx.x)*4;
    float4 v = *(const float4*)(X + i);
    g_XH[(i>>1) + 0] = __floats2half2_rn(v.x, v.y);
    g_XH[(i>>1) + 1] = __floats2half2_rn(v.z, v.w);
}

__global__ __launch_bounds__(256) void prep_w(const float* __restrict__ W0,
                                              const float* __restrict__ W1,
                                              const float* __restrict__ W2)
{
    int idx = blockIdx.x*256 + threadIdx.x;     // 0..49151
    int head = idx >> 14;
    int r    = idx & 16383;
    int n    = r >> 7;
    int kw   = r & 127;
    const float* W = (head == 0) ? W0 : (head == 1) ? W1 : W2;
    g_WH[idx] = __floats2half2_rn(W[(2*kw)*DDIM + n], W[(2*kw+1)*DDIM + n]);
}

// ---------------------------------------------------------------------------
// Fused heads + pointwise.  Grid: (BN/128, 3 heads), 256 threads.
// Mainloop: F = X @ W via fp16 mma (128x128 tile, K=256).
// Epilogue per head:
//   head 0: seg logits = F @ Wseg + bseg, softmax  -> o_logits, o_soft
//   head 1: fp16 F -> g_FsimH,  r = sum(fp16(F)^2) -> g_r
//   head 2: conf_logit = F . Wcl + bcl, sigmoid    -> o_conf, o_conflog
// No fp32 F ever hits DRAM.
// ---------------------------------------------------------------------------
__global__ __launch_bounds__(256)
void heads_fused(const float* __restrict__ bias0,
                 const float* __restrict__ bias1,
                 const float* __restrict__ bias2,
                 const float* __restrict__ Wseg, const float* __restrict__ bseg,
                 const float* __restrict__ Wcl,  const float* __restrict__ bcl,
                 float* __restrict__ o_soft, float* __restrict__ o_logits,
                 float* __restrict__ o_conf, float* __restrict__ o_conflog)
{
    __shared__ __align__(16) uint32_t smem_u[8320];  // sA/sB mainloop; Ts/red epilogue
    __shared__ __align__(16) float sW[64*52];        // Wseg k-half stage (head 0)
    __shared__ float sWcl[128];                      // head 2
    __shared__ float sRed[128];                      // heads 1/2 partner reduce

    uint32_t* sA = smem_u;
    uint32_t* sB = smem_u + 4104;
    float*    Ts = (float*)smem_u;                   // [128][65]
    float*    red = (float*)smem_u;                  // [128][52] after Ts is dead

    const int head = blockIdx.y;
    const int m0   = blockIdx.x * 128;
    const float* bias = (head == 0) ? bias0 : (head == 1) ? bias1 : bias2;

    const int tid  = threadIdx.x;
    const int lane = tid & 31;
    const int w    = tid >> 5;
    const int gID  = lane >> 2;
    const int tg   = lane & 3;
    const int wm   = w & 3;
    const int wn   = w >> 2;

    if (head == 2 && tid < 128) sWcl[tid] = Wcl[tid];

    const uint4* XA = (const uint4*)g_XH;
    const uint4* WB = (const uint4*)g_WH + head*4096;

    float c[2][8][4];
    #pragma unroll
    for (int mt = 0; mt < 2; ++mt)
        #pragma unroll
        for (int nt = 0; nt < 8; ++nt)
            #pragma unroll
            for (int rr = 0; rr < 4; ++rr) c[mt][nt][rr] = 0.f;

    for (int st = 0; st < 4; ++st) {
        __syncthreads();
        #pragma unroll
        for (int it = 0; it < 4; ++it) {
            int u   = tid + it*256;
            int row = u >> 3;
            int g4  = u & 7;
            int chl = g4 >> 1, kw4 = g4 & 1;
            uint4 va = XA[(size_t)(m0+row)*32 + st*8 + g4];
            uint4 vb = WB[(size_t)row*32 + st*8 + g4];
            int base = chl*CHSTR + row*8 + kw4;
            sA[base+0] = va.x; sA[base+2] = va.y; sA[base+4] = va.z; sA[base+6] = va.w;
            sB[base+0] = vb.x; sB[base+2] = vb.y; sB[base+4] = vb.z; sB[base+6] = vb.w;
        }
        __syncthreads();

        #pragma unroll
        for (int chl = 0; chl < 4; ++chl) {
            uint32_t a[2][4];
            #pragma unroll
            for (int mt = 0; mt < 2; ++mt) {
                int r0 = wm*32 + mt*16 + gID;
                int ad = chl*CHSTR + r0*8 + tg*2;
                uint2 p0 = *(const uint2*)(sA + ad);
                uint2 p1 = *(const uint2*)(sA + ad + 64);
                a[mt][0] = p0.x; a[mt][2] = p0.y;
                a[mt][1] = p1.x; a[mt][3] = p1.y;
            }
            #pragma unroll
            for (int nt = 0; nt < 8; ++nt) {
                int n  = wn*64 + nt*8 + gID;
                int bd = chl*CHSTR + n*8 + tg*2;
                uint2 bp = *(const uint2*)(sB + bd);
                mma_f16(c[0][nt], a[0][0], a[0][1], a[0][2], a[0][3], bp.x, bp.y);
                mma_f16(c[1][nt], a[1][0], a[1][1], a[1][2], a[1][3], bp.x, bp.y);
            }
        }
    }
    __syncthreads();

    // ---- epilogue ----
    const int row = tid & 127;     // point row within tile
    const int kh  = tid >> 7;      // which 32-k sub-half of the 64-col half

    float accS[50];
    float rs = 0.f, cd = 0.f;
    if (head == 0) {
        #pragma unroll
        for (int g = 0; g < 50; ++g) accS[g] = 0.f;
    }

    #pragma unroll
    for (int h = 0; h < 2; ++h) {
        // stage this column-half (with bias) into Ts
        if (wn == h) {
            #pragma unroll
            for (int mt = 0; mt < 2; ++mt) {
                int r0 = wm*32 + mt*16 + gID;
                #pragma unroll
                for (int nt = 0; nt < 8; ++nt) {
                    int c0l = nt*8 + tg*2;
                    int gc  = h*64 + c0l;
                    float b0 = bias[gc], b1 = bias[gc+1];
                    Ts[ r0   *65 + c0l    ] = c[mt][nt][0] + b0;
                    Ts[ r0   *65 + c0l + 1] = c[mt][nt][1] + b1;
                    Ts[(r0+8)*65 + c0l    ] = c[mt][nt][2] + b0;
                    Ts[(r0+8)*65 + c0l + 1] = c[mt][nt][3] + b1;
                }
            }
        }
        if (head == 0) {
            for (int i2 = tid; i2 < 64*NGROUP; i2 += 256) {
                int kl = i2 / NGROUP, g = i2 - kl*NGROUP;
                sW[kl*52 + g] = Wseg[(size_t)(h*64 + kl)*NGROUP + g];
            }
        }
        __syncthreads();

        if (head == 0) {
            #pragma unroll 4
            for (int kl = 0; kl < 32; ++kl) {
                float fv = Ts[row*65 + kh*32 + kl];
                const float4* wr = (const float4*)&sW[(kh*32 + kl)*52];
                #pragma unroll
                for (int g4 = 0; g4 < 12; ++g4) {
                    float4 ww = wr[g4];
                    accS[g4*4+0] += fv*ww.x; accS[g4*4+1] += fv*ww.y;
                    accS[g4*4+2] += fv*ww.z; accS[g4*4+3] += fv*ww.w;
                }
                float2 wt = *(const float2*)&sW[(kh*32 + kl)*52 + 48];
                accS[48] += fv*wt.x; accS[49] += fv*wt.y;
            }
        } else if (head == 1) {
            // fp16 store (coalesced)
            #pragma unroll
            for (int it = 0; it < 16; ++it) {
                int u  = tid + it*256;       // 128 rows x 32 half2
                int r2 = u >> 5;
                int c2 = u & 31;
                __half2 hv = __floats2half2_rn(Ts[r2*65 + c2*2], Ts[r2*65 + c2*2 + 1]);
                g_FsimH[(size_t)(m0+r2)*64 + h*32 + c2] = hv;
            }
            // r partial from fp16-rounded values
            #pragma unroll 8
            for (int kl = 0; kl < 32; ++kl) {
                float v = Ts[row*65 + kh*32 + kl];
                float f = __half2float(__float2half_rn(v));
                rs += f*f;
            }
        } else {
            #pragma unroll 8
            for (int kl = 0; kl < 32; ++kl)
                cd += Ts[row*65 + kh*32 + kl] * sWcl[h*64 + kh*32 + kl];
        }
        __syncthreads();
    }

    if (head == 0) {
        // partner reduce (kh=1 -> smem), then logits/softmax in kh=0 threads
        if (kh == 1) {
            #pragma unroll
            for (int g = 0; g < 50; ++g) red[row*52 + g] = accS[g];
        }
        __syncthreads();
        float mx = -1e30f, inv = 0.f;
        if (kh == 0) {
            #pragma unroll
            for (int g = 0; g < 50; ++g) {
                accS[g] += red[row*52 + g] + bseg[g];
                mx = fmaxf(mx, accS[g]);
            }
            float s = 0.f;
            #pragma unroll
            for (int g = 0; g < 50; ++g) s += expf(accS[g] - mx);
            inv = 1.0f / s;
        }
        __syncthreads();
        if (kh == 0) {
            #pragma unroll
            for (int g = 0; g < 50; ++g) red[row*52 + g] = accS[g];
        }
        __syncthreads();
        for (int i2 = tid; i2 < 128*NGROUP; i2 += 256) {
            int r2 = i2 / NGROUP, g = i2 - r2*NGROUP;
            o_logits[(size_t)m0*NGROUP + i2] = red[r2*52 + g];
        }
        __syncthreads();
        if (kh == 0) {
            #pragma unroll
            for (int g = 0; g < 50; ++g) red[row*52 + g] = expf(accS[g] - mx)*inv;
        }
        __syncthreads();
        for (int i2 = tid; i2 < 128*NGROUP; i2 += 256) {
            int r2 = i2 / NGROUP, g = i2 - r2*NGROUP;
            o_soft[(size_t)m0*NGROUP + i2] = red[r2*52 + g];
        }
    } else if (head == 1) {
        if (kh == 1) sRed[row] = rs;
        __syncthreads();
        if (kh == 0) g_r[m0 + row] = rs + sRed[row];
    } else {
        if (kh == 1) sRed[row] = cd;
        __syncthreads();
        if (kh == 0) {
            float cl = cd + sRed[row] + bcl[0];
            o_conflog[m0 + row] = cl;
            o_conf[m0 + row]    = 1.0f / (1.0f + expf(-cl));
        }
    }
}

// ---------------------------------------------------------------------------
// Gram / simmat via fp16 mma: 128x128 tiles, triangular grid, symmetric write.
//   out[b,m,n] = max(10*(r[m] - 2*FsimH[m].FsimH[n] + r[n]), 0)
// ---------------------------------------------------------------------------
#define GTILE 128

__global__ __launch_bounds__(256)
void gram_mma(float* __restrict__ out)
{
    __shared__ __align__(16) uint32_t smem_u[8320];   // sA(4104)+sB(4104); Ts alias
    __shared__ float rm_s[GTILE], rn_s[GTILE];

    uint32_t* sA = smem_u;
    uint32_t* sB = smem_u + 4104;
    float*    Ts = (float*)smem_u;                    // [128][65]

    const int b = blockIdx.z;
    const int t = blockIdx.x;
    int j = (int)((sqrtf(8.0f*(float)t + 1.0f) - 1.0f) * 0.5f);
    while ((j+1)*(j+2)/2 <= t) ++j;
    while (j*(j+1)/2 > t)      --j;
    const int i  = t - j*(j+1)/2;       // i <= j
    const int m0 = i*GTILE, n0 = j*GTILE;
    const bool diag = (i == j);

    const uint4* FH = (const uint4*)g_FsimH + (size_t)b*NPT*16;
    const float* rb = g_r + b*NPT;

    const int tid  = threadIdx.x;
    const int lane = tid & 31;
    const int w    = tid >> 5;
    const int gID  = lane >> 2;
    const int tg   = lane & 3;
    const int wm   = w & 3;
    const int wn   = w >> 2;

    if (tid < GTILE) {
        rm_s[tid] = rb[m0 + tid];
        rn_s[tid] = rb[n0 + tid];
    }

    float c[2][8][4];
    #pragma unroll
    for (int mt = 0; mt < 2; ++mt)
        #pragma unroll
        for (int nt = 0; nt < 8; ++nt)
            #pragma unroll
            for (int rr = 0; rr < 4; ++rr) c[mt][nt][rr] = 0.f;

    const uint32_t* sBr = diag ? sA : sB;

    for (int st = 0; st < 2; ++st) {
        __syncthreads();
        #pragma unroll
        for (int it = 0; it < 4; ++it) {
            int u   = tid + it*256;
            int row = u >> 3;
            int g4  = u & 7;
            int chl = g4 >> 1, kw4 = g4 & 1;
            int base = chl*CHSTR + row*8 + kw4;
            uint4 va = FH[(size_t)(m0+row)*16 + st*8 + g4];
            sA[base+0] = va.x; sA[base+2] = va.y; sA[base+4] = va.z; sA[base+6] = va.w;
            if (!diag) {
                uint4 vb = FH[(size_t)(n0+row)*16 + st*8 + g4];
                sB[base+0] = vb.x; sB[base+2] = vb.y; sB[base+4] = vb.z; sB[base+6] = vb.w;
            }
        }
        __syncthreads();

        #pragma unroll
        for (int chl = 0; chl < 4; ++chl) {
            uint32_t a[2][4];
            #pragma unroll
            for (int mt = 0; mt < 2; ++mt) {
                int r0 = wm*32 + mt*16 + gID;
                int ad = chl*CHSTR + r0*8 + tg*2;
                uint2 p0 = *(const uint2*)(sA + ad);
                uint2 p1 = *(const uint2*)(sA + ad + 64);
                a[mt][0] = p0.x; a[mt][2] = p0.y;
                a[mt][1] = p1.x; a[mt][3] = p1.y;
            }
            #pragma unroll
            for (int nt = 0; nt < 8; ++nt) {
                int n  = wn*64 + nt*8 + gID;
                int bd = chl*CHSTR + n*8 + tg*2;
                uint2 bp = *(const uint2*)(sBr + bd);
                mma_f16(c[0][nt], a[0][0], a[0][1], a[0][2], a[0][3], bp.x, bp.y);
                mma_f16(c[1][nt], a[1][0], a[1][1], a[1][2], a[1][3], bp.x, bp.y);
            }
        }
    }
    __syncthreads();

    const size_t base = (size_t)b * NPT * NPT;

    #pragma unroll
    for (int h = 0; h < 2; ++h) {
        if (wn == h) {
            #pragma unroll
            for (int mt = 0; mt < 2; ++mt) {
                int r0 = wm*32 + mt*16 + gID;
                float rm0 = rm_s[r0], rm1 = rm_s[r0 + 8];
                #pragma unroll
                for (int nt = 0; nt < 8; ++nt) {
                    int c0l = nt*8 + tg*2;
                    int gc0 = h*64 + c0l;
                    float rn0 = rn_s[gc0], rn1 = rn_s[gc0 + 1];
                    float d00 = fmaxf(10.0f*(rm0 + rn0 - 2.0f*c[mt][nt][0]), 0.0f);
                    float d01 = fmaxf(10.0f*(rm0 + rn1 - 2.0f*c[mt][nt][1]), 0.0f);
                    float d10 = fmaxf(10.0f*(rm1 + rn0 - 2.0f*c[mt][nt][2]), 0.0f);
                    float d11 = fmaxf(10.0f*(rm1 + rn1 - 2.0f*c[mt][nt][3]), 0.0f);
                    if (diag) {
                        if (r0   == gc0)   d00 = 0.0f;
                        if (r0   == gc0+1) d01 = 0.0f;
                        if (r0+8 == gc0)   d10 = 0.0f;
                        if (r0+8 == gc0+1) d11 = 0.0f;
                    }
                    Ts[ r0   *65 + c0l    ] = d00;
                    Ts[ r0   *65 + c0l + 1] = d01;
                    Ts[(r0+8)*65 + c0l    ] = d10;
                    Ts[(r0+8)*65 + c0l + 1] = d11;
                }
            }
        }
        __syncthreads();

        #pragma unroll 4
        for (int it = 0; it < 32; ++it) {
            int idx = tid + it*256;
            int row = idx >> 6, cc = idx & 63;
            __stcs(&out[base + (size_t)(m0+row)*NPT + n0 + h*64 + cc], Ts[row*65 + cc]);
        }
        if (!diag) {
            #pragma unroll 4
            for (int it = 0; it < 32; ++it) {
                int idx = tid + it*256;
                int cc = idx >> 7, row = idx & 127;
                __stcs(&out[base + (size_t)(n0 + h*64 + cc)*NPT + m0 + row], Ts[row*65 + cc]);
            }
        }
        __syncthreads();
    }
}

// ---------------------------------------------------------------------------
extern "C" void kernel_launch(void* const* d_in, const int* in_sizes, int n_in,
                              void* d_out, int out_size)
{
    const float* X     = (const float*)d_in[0];
    const float* Wsem  = (const float*)d_in[1];
    const float* bsem  = (const float*)d_in[2];
    const float* Wseg  = (const float*)d_in[3];
    const float* bseg  = (const float*)d_in[4];
    const float* Wsim  = (const float*)d_in[5];
    const float* bsim  = (const float*)d_in[6];
    const float* Wconf = (const float*)d_in[7];
    const float* bconf = (const float*)d_in[8];
    const float* Wcl   = (const float*)d_in[9];
    const float* bcl   = (const float*)d_in[10];

    float* out       = (float*)d_out;
    float* o_soft    = out + OFF_SOFT;
    float* o_logits  = out + OFF_LOGITS;
    float* o_sim     = out + OFF_SIM;
    float* o_conf    = out + OFF_CONF;
    float* o_conflog = out + OFF_CONFLOG;

    prep_x<<<BN*CDIM/1024, 256>>>(X);
    prep_w<<<192, 256>>>(Wsem, Wsim, Wconf);

    heads_fused<<<dim3(BN/128, 3), 256>>>(bsem, bsim, bconf,
                                          Wseg, bseg, Wcl, bcl,
                                          o_soft, o_logits, o_conf, o_conflog);

    const int ntiles = (NPT/GTILE) * (NPT/GTILE + 1) / 2;   // 528
    gram_mma<<<dim3(ntiles, 1, BATCH), 256>>>(o_sim);
}

// round 9
// speedup vs baseline: 4.3451x; 1.0213x over previous
#include <cuda_runtime.h>
#include <cuda_fp16.h>
#include <cstdint>

#define BATCH  4
#define NPT    4096
#define CDIM   256
#define DDIM   128
#define NGROUP 50
#define BN     (BATCH*NPT)

#define OFF_SOFT    0
#define OFF_LOGITS  819200
#define OFF_SIM     1638400
#define OFF_CONF    68747264
#define OFF_CONFLOG 68763648

// Scratch (device globals: allocation-free)
__device__ __half2 g_FsimH[BN*DDIM/2];     // fp16 Fsim, row-major k-pairs
__device__ __half2 g_XH[BN*CDIM/2];        // fp16 X, row-major k-pairs
__device__ __half2 g_WH[3*DDIM*CDIM/2];    // [head][n][kw] = {W[2kw][n], W[2kw+1][n]}
__device__ float   g_r[BN];

#define CHSTR 1026   // words per k16-chunk in smem frag layout (1024 + 2 pad)

__device__ __forceinline__ void mma_f16(float c[4],
                                        uint32_t a0, uint32_t a1, uint32_t a2, uint32_t a3,
                                        uint32_t b0, uint32_t b1) {
    asm volatile(
        "mma.sync.aligned.m16n8k16.row.col.f32.f16.f16.f32 "
        "{%0,%1,%2,%3}, {%4,%5,%6,%7}, {%8,%9}, {%0,%1,%2,%3};"
        : "+f"(c[0]), "+f"(c[1]), "+f"(c[2]), "+f"(c[3])
        : "r"(a0), "r"(a1), "r"(a2), "r"(a3), "r"(b0), "r"(b1));
}

// ---------------------------------------------------------------------------
// prep kernels: pack X and W into fp16 layouts
// ---------------------------------------------------------------------------
__global__ __launch_bounds__(256) void prep_x(const float* __restrict__ X)
{
    int i = (blockIdx.x*256 + threadIdx.x)*4;
    float4 v = *(const float4*)(X + i);
    g_XH[(i>>1) + 0] = __floats2half2_rn(v.x, v.y);
    g_XH[(i>>1) + 1] = __floats2half2_rn(v.z, v.w);
}

__global__ __launch_bounds__(256) void prep_w(const float* __restrict__ W0,
                                              const float* __restrict__ W1,
                                              const float* __restrict__ W2)
{
    int idx = blockIdx.x*256 + threadIdx.x;     // 0..49151
    int head = idx >> 14;
    int r    = idx & 16383;
    int n    = r >> 7;
    int kw   = r & 127;
    const float* W = (head == 0) ? W0 : (head == 1) ? W1 : W2;
    g_WH[idx] = __floats2half2_rn(W[(2*kw)*DDIM + n], W[(2*kw+1)*DDIM + n]);
}

// ---------------------------------------------------------------------------
// Fused heads + pointwise.  Grid: (BN/128, 3 heads), 256 threads.
//   head 0: seg logits + softmax -> o_logits, o_soft
//   head 1: fp16 F -> g_FsimH,  r -> g_r
//   head 2: conf sigmoid        -> o_conf, o_conflog
// ---------------------------------------------------------------------------
__global__ __launch_bounds__(256)
void heads_fused(const float* __restrict__ bias0,
                 const float* __restrict__ bias1,
                 const float* __restrict__ bias2,
                 const float* __restrict__ Wseg, const float* __restrict__ bseg,
                 const float* __restrict__ Wcl,  const float* __restrict__ bcl,
                 float* __restrict__ o_soft, float* __restrict__ o_logits,
                 float* __restrict__ o_conf, float* __restrict__ o_conflog)
{
    __shared__ __align__(16) uint32_t smem_u[8320];  // sA/sB mainloop; Ts/red epilogue
    __shared__ __align__(16) float sW[64*52];        // Wseg k-half stage (head 0)
    __shared__ float sWcl[128];                      // head 2
    __shared__ float sRed[128];                      // heads 1/2 partner reduce

    uint32_t* sA = smem_u;
    uint32_t* sB = smem_u + 4104;
    float*    Ts = (float*)smem_u;                   // [128][65]
    float*    red = (float*)smem_u;                  // [128][52] after Ts is dead

    const int head = blockIdx.y;
    const int m0   = blockIdx.x * 128;
    const float* bias = (head == 0) ? bias0 : (head == 1) ? bias1 : bias2;

    const int tid  = threadIdx.x;
    const int lane = tid & 31;
    const int w    = tid >> 5;
    const int gID  = lane >> 2;
    const int tg   = lane & 3;
    const int wm   = w & 3;
    const int wn   = w >> 2;

    if (head == 2 && tid < 128) sWcl[tid] = Wcl[tid];

    const uint4* XA = (const uint4*)g_XH;
    const uint4* WB = (const uint4*)g_WH + head*4096;

    float c[2][8][4];
    #pragma unroll
    for (int mt = 0; mt < 2; ++mt)
        #pragma unroll
        for (int nt = 0; nt < 8; ++nt)
            #pragma unroll
            for (int rr = 0; rr < 4; ++rr) c[mt][nt][rr] = 0.f;

    for (int st = 0; st < 4; ++st) {
        __syncthreads();
        #pragma unroll
        for (int it = 0; it < 4; ++it) {
            int u   = tid + it*256;
            int row = u >> 3;
            int g4  = u & 7;
            int chl = g4 >> 1, kw4 = g4 & 1;
            uint4 va = XA[(size_t)(m0+row)*32 + st*8 + g4];
            uint4 vb = WB[(size_t)row*32 + st*8 + g4];
            int base = chl*CHSTR + row*8 + kw4;
            sA[base+0] = va.x; sA[base+2] = va.y; sA[base+4] = va.z; sA[base+6] = va.w;
            sB[base+0] = vb.x; sB[base+2] = vb.y; sB[base+4] = vb.z; sB[base+6] = vb.w;
        }
        __syncthreads();

        #pragma unroll
        for (int chl = 0; chl < 4; ++chl) {
            uint32_t a[2][4];
            #pragma unroll
            for (int mt = 0; mt < 2; ++mt) {
                int r0 = wm*32 + mt*16 + gID;
                int ad = chl*CHSTR + r0*8 + tg*2;
                uint2 p0 = *(const uint2*)(sA + ad);
                uint2 p1 = *(const uint2*)(sA + ad + 64);
                a[mt][0] = p0.x; a[mt][2] = p0.y;
                a[mt][1] = p1.x; a[mt][3] = p1.y;
            }
            #pragma unroll
            for (int nt = 0; nt < 8; ++nt) {
                int n  = wn*64 + nt*8 + gID;
                int bd = chl*CHSTR + n*8 + tg*2;
                uint2 bp = *(const uint2*)(sB + bd);
                mma_f16(c[0][nt], a[0][0], a[0][1], a[0][2], a[0][3], bp.x, bp.y);
                mma_f16(c[1][nt], a[1][0], a[1][1], a[1][2], a[1][3], bp.x, bp.y);
            }
        }
    }
    __syncthreads();

    // ---- epilogue ----
    const int row = tid & 127;     // point row within tile
    const int kh  = tid >> 7;      // which 32-k sub-half of the 64-col half

    float accS[50];
    float rs = 0.f, cd = 0.f;
    if (head == 0) {
        #pragma unroll
        for (int g = 0; g < 50; ++g) accS[g] = 0.f;
    }

    #pragma unroll
    for (int h = 0; h < 2; ++h) {
        // stage this column-half (with bias) into Ts
        if (wn == h) {
            #pragma unroll
            for (int mt = 0; mt < 2; ++mt) {
                int r0 = wm*32 + mt*16 + gID;
                #pragma unroll
                for (int nt = 0; nt < 8; ++nt) {
                    int c0l = nt*8 + tg*2;
                    int gc  = h*64 + c0l;
                    float b0 = bias[gc], b1 = bias[gc+1];
                    Ts[ r0   *65 + c0l    ] = c[mt][nt][0] + b0;
                    Ts[ r0   *65 + c0l + 1] = c[mt][nt][1] + b1;
                    Ts[(r0+8)*65 + c0l    ] = c[mt][nt][2] + b0;
                    Ts[(r0+8)*65 + c0l + 1] = c[mt][nt][3] + b1;
                }
            }
        }
        if (head == 0) {
            for (int i2 = tid; i2 < 64*NGROUP; i2 += 256) {
                int kl = i2 / NGROUP, g = i2 - kl*NGROUP;
                sW[kl*52 + g] = Wseg[(size_t)(h*64 + kl)*NGROUP + g];
            }
        }
        __syncthreads();

        if (head == 0) {
            #pragma unroll 4
            for (int kl = 0; kl < 32; ++kl) {
                float fv = Ts[row*65 + kh*32 + kl];
                const float4* wr = (const float4*)&sW[(kh*32 + kl)*52];
                #pragma unroll
                for (int g4 = 0; g4 < 12; ++g4) {
                    float4 ww = wr[g4];
                    accS[g4*4+0] += fv*ww.x; accS[g4*4+1] += fv*ww.y;
                    accS[g4*4+2] += fv*ww.z; accS[g4*4+3] += fv*ww.w;
                }
                float2 wt = *(const float2*)&sW[(kh*32 + kl)*52 + 48];
                accS[48] += fv*wt.x; accS[49] += fv*wt.y;
            }
        } else if (head == 1) {
            #pragma unroll
            for (int it = 0; it < 16; ++it) {
                int u  = tid + it*256;       // 128 rows x 32 half2
                int r2 = u >> 5;
                int c2 = u & 31;
                __half2 hv = __floats2half2_rn(Ts[r2*65 + c2*2], Ts[r2*65 + c2*2 + 1]);
                g_FsimH[(size_t)(m0+r2)*64 + h*32 + c2] = hv;
            }
            #pragma unroll 8
            for (int kl = 0; kl < 32; ++kl) {
                float v = Ts[row*65 + kh*32 + kl];
                float f = __half2float(__float2half_rn(v));
                rs += f*f;
            }
        } else {
            #pragma unroll 8
            for (int kl = 0; kl < 32; ++kl)
                cd += Ts[row*65 + kh*32 + kl] * sWcl[h*64 + kh*32 + kl];
        }
        __syncthreads();
    }

    if (head == 0) {
        if (kh == 1) {
            #pragma unroll
            for (int g = 0; g < 50; ++g) red[row*52 + g] = accS[g];
        }
        __syncthreads();
        float mx = -1e30f, inv = 0.f;
        if (kh == 0) {
            #pragma unroll
            for (int g = 0; g < 50; ++g) {
                accS[g] += red[row*52 + g] + bseg[g];
                mx = fmaxf(mx, accS[g]);
            }
            float s = 0.f;
            #pragma unroll
            for (int g = 0; g < 50; ++g) s += expf(accS[g] - mx);
            inv = 1.0f / s;
        }
        __syncthreads();
        if (kh == 0) {
            #pragma unroll
            for (int g = 0; g < 50; ++g) red[row*52 + g] = accS[g];
        }
        __syncthreads();
        for (int i2 = tid; i2 < 128*NGROUP; i2 += 256) {
            int r2 = i2 / NGROUP, g = i2 - r2*NGROUP;
            o_logits[(size_t)m0*NGROUP + i2] = red[r2*52 + g];
        }
        __syncthreads();
        if (kh == 0) {
            #pragma unroll
            for (int g = 0; g < 50; ++g) red[row*52 + g] = expf(accS[g] - mx)*inv;
        }
        __syncthreads();
        for (int i2 = tid; i2 < 128*NGROUP; i2 += 256) {
            int r2 = i2 / NGROUP, g = i2 - r2*NGROUP;
            o_soft[(size_t)m0*NGROUP + i2] = red[r2*52 + g];
        }
    } else if (head == 1) {
        if (kh == 1) sRed[row] = rs;
        __syncthreads();
        if (kh == 0) g_r[m0 + row] = rs + sRed[row];
    } else {
        if (kh == 1) sRed[row] = cd;
        __syncthreads();
        if (kh == 0) {
            float cl = cd + sRed[row] + bcl[0];
            o_conflog[m0 + row] = cl;
            o_conf[m0 + row]    = 1.0f / (1.0f + expf(-cl));
        }
    }
}

// ---------------------------------------------------------------------------
// Gram / simmat via fp16 mma: 128x128 tiles, triangular grid, symmetric write.
//   out[b,m,n] = max(10*(r[m] - 2*FsimH[m].FsimH[n] + r[n]), 0)
// Epilogue v2: direct tile stored from registers (float2, sector-aligned);
// transposed tile through conflict-free Tt[c][r] stage with float4 LDS/STG.
// ---------------------------------------------------------------------------
#define GTILE 128
#define TTSTR 132    // Tt row stride in floats (528B: 16B-aligned, conflict-free)

__global__ __launch_bounds__(256)
void gram_mma(float* __restrict__ out)
{
    __shared__ __align__(16) float smem_f[8448];      // mainloop sA/sB; Tt half-stage
    __shared__ float rm_s[GTILE], rn_s[GTILE];

    uint32_t* sA = (uint32_t*)smem_f;
    uint32_t* sB = (uint32_t*)smem_f + 4104;
    float*    Tt = smem_f;                            // [64][TTSTR] per half

    const int b = blockIdx.z;
    const int t = blockIdx.x;
    int j = (int)((sqrtf(8.0f*(float)t + 1.0f) - 1.0f) * 0.5f);
    while ((j+1)*(j+2)/2 <= t) ++j;
    while (j*(j+1)/2 > t)      --j;
    const int i  = t - j*(j+1)/2;       // i <= j
    const int m0 = i*GTILE, n0 = j*GTILE;
    const bool diag = (i == j);

    const uint4* FH = (const uint4*)g_FsimH + (size_t)b*NPT*16;
    const float* rb = g_r + b*NPT;

    const int tid  = threadIdx.x;
    const int lane = tid & 31;
    const int w    = tid >> 5;
    const int gID  = lane >> 2;
    const int tg   = lane & 3;
    const int wm   = w & 3;
    const int wn   = w >> 2;

    if (tid < GTILE) {
        rm_s[tid] = rb[m0 + tid];
        rn_s[tid] = rb[n0 + tid];
    }

    float c[2][8][4];
    #pragma unroll
    for (int mt = 0; mt < 2; ++mt)
        #pragma unroll
        for (int nt = 0; nt < 8; ++nt)
            #pragma unroll
            for (int rr = 0; rr < 4; ++rr) c[mt][nt][rr] = 0.f;

    const uint32_t* sBr = diag ? sA : sB;

    for (int st = 0; st < 2; ++st) {
        __syncthreads();
        #pragma unroll
        for (int it = 0; it < 4; ++it) {
            int u   = tid + it*256;
            int row = u >> 3;
            int g4  = u & 7;
            int chl = g4 >> 1, kw4 = g4 & 1;
            int base = chl*CHSTR + row*8 + kw4;
            uint4 va = FH[(size_t)(m0+row)*16 + st*8 + g4];
            sA[base+0] = va.x; sA[base+2] = va.y; sA[base+4] = va.z; sA[base+6] = va.w;
            if (!diag) {
                uint4 vb = FH[(size_t)(n0+row)*16 + st*8 + g4];
                sB[base+0] = vb.x; sB[base+2] = vb.y; sB[base+4] = vb.z; sB[base+6] = vb.w;
            }
        }
        __syncthreads();

        #pragma unroll
        for (int chl = 0; chl < 4; ++chl) {
            uint32_t a[2][4];
            #pragma unroll
            for (int mt = 0; mt < 2; ++mt) {
                int r0 = wm*32 + mt*16 + gID;
                int ad = chl*CHSTR + r0*8 + tg*2;
                uint2 p0 = *(const uint2*)(sA + ad);
                uint2 p1 = *(const uint2*)(sA + ad + 64);
                a[mt][0] = p0.x; a[mt][2] = p0.y;
                a[mt][1] = p1.x; a[mt][3] = p1.y;
            }
            #pragma unroll
            for (int nt = 0; nt < 8; ++nt) {
                int n  = wn*64 + nt*8 + gID;
                int bd = chl*CHSTR + n*8 + tg*2;
                uint2 bp = *(const uint2*)(sBr + bd);
                mma_f16(c[0][nt], a[0][0], a[0][1], a[0][2], a[0][3], bp.x, bp.y);
                mma_f16(c[1][nt], a[1][0], a[1][1], a[1][2], a[1][3], bp.x, bp.y);
            }
        }
    }

    // ---- compute d in registers ----
    const int rA = wm*32 + gID;            // fragment rows rA, rA+8, rA+16(+mt*16), ...
    #pragma unroll
    for (int mt = 0; mt < 2; ++mt) {
        int r0 = rA + mt*16;
        float rm0 = rm_s[r0], rm1 = rm_s[r0 + 8];
        #pragma unroll
        for (int nt = 0; nt < 8; ++nt) {
            int gc0 = wn*64 + nt*8 + tg*2;
            float rn0 = rn_s[gc0], rn1 = rn_s[gc0 + 1];
            float d00 = fmaxf(10.0f*(rm0 + rn0 - 2.0f*c[mt][nt][0]), 0.0f);
            float d01 = fmaxf(10.0f*(rm0 + rn1 - 2.0f*c[mt][nt][1]), 0.0f);
            float d10 = fmaxf(10.0f*(rm1 + rn0 - 2.0f*c[mt][nt][2]), 0.0f);
            float d11 = fmaxf(10.0f*(rm1 + rn1 - 2.0f*c[mt][nt][3]), 0.0f);
            if (diag) {
                if (r0   == gc0)   d00 = 0.0f;
                if (r0   == gc0+1) d01 = 0.0f;
                if (r0+8 == gc0)   d10 = 0.0f;
                if (r0+8 == gc0+1) d11 = 0.0f;
            }
            c[mt][nt][0] = d00; c[mt][nt][1] = d01;
            c[mt][nt][2] = d10; c[mt][nt][3] = d11;
        }
    }

    const size_t base = (size_t)b * NPT * NPT;

    // ---- direct tile: straight from registers, float2 streaming stores ----
    {
        float* orow = out + base + (size_t)m0*NPT + n0;
        #pragma unroll
        for (int mt = 0; mt < 2; ++mt) {
            int r0 = rA + mt*16;
            #pragma unroll
            for (int nt = 0; nt < 8; ++nt) {
                int gc0 = wn*64 + nt*8 + tg*2;
                __stcs((float2*)&orow[(size_t)r0*NPT + gc0],
                       make_float2(c[mt][nt][0], c[mt][nt][1]));
                __stcs((float2*)&orow[(size_t)(r0+8)*NPT + gc0],
                       make_float2(c[mt][nt][2], c[mt][nt][3]));
            }
        }
    }

    // ---- transposed tile (skip on diagonal): Tt stage + float4 stores ----
    if (!diag) {
        #pragma unroll
        for (int h = 0; h < 2; ++h) {
            __syncthreads();
            if (wn == h) {
                #pragma unroll
                for (int mt = 0; mt < 2; ++mt) {
                    int r0 = rA + mt*16;
                    #pragma unroll
                    for (int nt = 0; nt < 8; ++nt) {
                        int cl = nt*8 + tg*2;      // local col within half
                        Tt[ cl   *TTSTR + r0    ] = c[mt][nt][0];
                        Tt[(cl+1)*TTSTR + r0    ] = c[mt][nt][1];
                        Tt[ cl   *TTSTR + r0 + 8] = c[mt][nt][2];
                        Tt[(cl+1)*TTSTR + r0 + 8] = c[mt][nt][3];
                    }
                }
            }
            __syncthreads();
            // 64 cols x 128 rows = 2048 float4; 8 per thread
            float* ocol = out + base + (size_t)(n0 + h*64)*NPT + m0;
            #pragma unroll
            for (int it = 0; it < 8; ++it) {
                int idx = tid + it*256;          // 0..2047
                int cc  = idx >> 5;              // col 0..63
                int f4  = idx & 31;              // float4 slot 0..31
                float4 vv = *(float4*)&Tt[cc*TTSTR + f4*4];
                __stcs((float4*)&ocol[(size_t)cc*NPT + f4*4], vv);
            }
        }
    }
}

// ---------------------------------------------------------------------------
extern "C" void kernel_launch(void* const* d_in, const int* in_sizes, int n_in,
                              void* d_out, int out_size)
{
    const float* X     = (const float*)d_in[0];
    const float* Wsem  = (const float*)d_in[1];
    const float* bsem  = (const float*)d_in[2];
    const float* Wseg  = (const float*)d_in[3];
    const float* bseg  = (const float*)d_in[4];
    const float* Wsim  = (const float*)d_in[5];
    const float* bsim  = (const float*)d_in[6];
    const float* Wconf = (const float*)d_in[7];
    const float* bconf = (const float*)d_in[8];
    const float* Wcl   = (const float*)d_in[9];
    const float* bcl   = (const float*)d_in[10];

    float* out       = (float*)d_out;
    float* o_soft    = out + OFF_SOFT;
    float* o_logits  = out + OFF_LOGITS;
    float* o_sim     = out + OFF_SIM;
    float* o_conf    = out + OFF_CONF;
    float* o_conflog = out + OFF_CONFLOG;

    prep_x<<<BN*CDIM/1024, 256>>>(X);
    prep_w<<<192, 256>>>(Wsem, Wsim, Wconf);

    heads_fused<<<dim3(BN/128, 3), 256>>>(bsem, bsim, bconf,
                                          Wseg, bseg, Wcl, bcl,
                                          o_soft, o_logits, o_conf, o_conflog);

    const int ntiles = (NPT/GTILE) * (NPT/GTILE + 1) / 2;   // 528
    gram_mma<<<dim3(ntiles, 1, BATCH), 256>>>(o_sim);
}